// round 8
// baseline (speedup 1.0000x reference)
#include <cuda_runtime.h>
#include <math_constants.h>
#include <stdint.h>

#define B  32
#define N  8192
#define K  128
#define PS 32

#define CAPK 1024

typedef unsigned long long u64;

// Scratch (allocation-free rule: __device__ globals)
__device__ int   g_fps_idx[B * K];
__device__ float g_centers[B * K * 3];
__device__ int   g_knn[B * K * PS];

// ---------------------------------------------------------------------------
// f32x2 packed helpers (one fma-pipe instr = 2 IEEE .rn ops, bit-identical)
// ---------------------------------------------------------------------------
__device__ __forceinline__ u64 pack2(float lo, float hi) {
    u64 r; asm("mov.b64 %0, {%1, %2};" : "=l"(r) : "f"(lo), "f"(hi)); return r;
}
__device__ __forceinline__ float2 unpack2(u64 v) {
    float2 f; asm("mov.b64 {%0, %1}, %2;" : "=f"(f.x), "=f"(f.y) : "l"(v)); return f;
}
__device__ __forceinline__ u64 add2(u64 a, u64 b) {
    u64 d; asm("add.rn.f32x2 %0, %1, %2;" : "=l"(d) : "l"(a), "l"(b)); return d;
}
__device__ __forceinline__ u64 mul2(u64 a, u64 b) {
    u64 d; asm("mul.rn.f32x2 %0, %1, %2;" : "=l"(d) : "l"(a), "l"(b)); return d;
}
__device__ __forceinline__ u64 fma2(u64 a, u64 b, u64 c) {
    u64 d; asm("fma.rn.f32x2 %0, %1, %2, %3;" : "=l"(d) : "l"(a), "l"(b), "l"(c)); return d;
}

// ---------------------------------------------------------------------------
// FPS (measured 72us — UNCHANGED)
// ---------------------------------------------------------------------------
extern "C" __global__ void __launch_bounds__(1024, 1)
fps_kernel(const float* __restrict__ points) {
    extern __shared__ float pts[];      // [N*3] = 96KB
    __shared__ unsigned s_maxb[K];
    __shared__ int      s_idx[K];

    const int b = blockIdx.x;
    const int t = threadIdx.x;
    const float* gp = points + (size_t)b * N * 3;

    for (int i = t; i < N * 3; i += 1024) pts[i] = gp[i];
    if (t < K) { s_maxb[t] = 0u; s_idx[t] = 0x7fffffff; }
    __syncthreads();

    u64 px2[4], py2[4], pz2[4];
    float md[8];
#pragma unroll
    for (int j = 0; j < 4; j++) {
        int nlo = t + (2 * j) * 1024;
        int nhi = t + (2 * j + 1) * 1024;
        px2[j] = pack2(pts[3 * nlo + 0], pts[3 * nhi + 0]);
        py2[j] = pack2(pts[3 * nlo + 1], pts[3 * nhi + 1]);
        pz2[j] = pack2(pts[3 * nlo + 2], pts[3 * nhi + 2]);
        md[2 * j] = CUDART_INF_F; md[2 * j + 1] = CUDART_INF_F;
    }

    int cur = 0;
    const int lane = t & 31;
    for (int k = 0; k < K; k++) {
        float cx = pts[3 * cur + 0];
        float cy = pts[3 * cur + 1];
        float cz = pts[3 * cur + 2];
        if (t == 0) {
            g_fps_idx[b * K + k] = cur;
            g_centers[(b * K + k) * 3 + 0] = cx;
            g_centers[(b * K + k) * 3 + 1] = cy;
            g_centers[(b * K + k) * 3 + 2] = cz;
        }
        u64 nc2x = pack2(-cx, -cx);
        u64 nc2y = pack2(-cy, -cy);
        u64 nc2z = pack2(-cz, -cz);
#pragma unroll
        for (int j = 0; j < 4; j++) {
            u64 dx = add2(px2[j], nc2x);
            u64 dy = add2(py2[j], nc2y);
            u64 dz = add2(pz2[j], nc2z);
            u64 d  = mul2(dx, dx);
            d = fma2(dy, dy, d);
            d = fma2(dz, dz, d);
            float2 f = unpack2(d);
            md[2 * j]     = fminf(md[2 * j],     f.x);
            md[2 * j + 1] = fminf(md[2 * j + 1], f.y);
        }
        float tv = fmaxf(fmaxf(fmaxf(md[0], md[1]), fmaxf(md[2], md[3])),
                         fmaxf(fmaxf(md[4], md[5]), fmaxf(md[6], md[7])));
        unsigned wv = __reduce_max_sync(0xffffffffu, __float_as_uint(tv));
        if (lane == 0) atomicMax(&s_maxb[k], wv);
        __syncthreads();
        const unsigned mb = s_maxb[k];
        if (wv == mb) {
            int li = 0x7fffffff;
#pragma unroll
            for (int s = 0; s < 8; s++) {
                if (__float_as_uint(md[s]) == mb) li = min(li, t + s * 1024);
            }
            if (li != 0x7fffffff) atomicMin(&s_idx[k], li);
        }
        __syncthreads();
        cur = s_idx[k];
    }
}

// ---------------------------------------------------------------------------
// Exact key (explicit intrinsics, bit-identical everywhere it is called)
// ---------------------------------------------------------------------------
__device__ __forceinline__ unsigned d2key(float px, float py, float pz,
                                          float cx, float cy, float cz, float cc) {
    float pp  = __fmaf_rn(pz, pz, __fmaf_rn(py, py, __fmul_rn(px, px)));
    float dot = __fmaf_rn(cz, pz, __fmaf_rn(cy, py, __fmul_rn(cx, px)));
    float d2  = __fmaf_rn(-2.0f, dot, __fadd_rn(cc, pp));
    unsigned bits = __float_as_uint(d2);
    return (bits & 0x80000000u) ? ~bits : (bits | 0x80000000u);
}

// ---------------------------------------------------------------------------
// KNN: 1 row/CTA, 256 threads. Full u32 keys in SMEM (32KB). Threshold via
// exact binary search on the key VALUE (monotone count; no bin-granularity
// failure mode). Typical path: 1 count pass. Collect + stable rank sort.
// Tie-overflow fallback runs over SMEM keys (cheap), never global.
// ---------------------------------------------------------------------------
extern "C" __global__ void __launch_bounds__(256)
knn_kernel(const float* __restrict__ points) {
    extern __shared__ char sm[];
    unsigned* s_key  = (unsigned*)sm;                       // N*4   = 32KB
    int*      s_cidx = (int*)(sm + N * 4);                  // CAPK*4=  4KB
    unsigned* s_ckey = (unsigned*)(sm + N * 4 + CAPK * 4);  // CAPK*4=  4KB

    __shared__ unsigned s_wmin[8];
    __shared__ int      s_cnt;
    __shared__ u64      s_min8[8];
    __shared__ u64      s_last;

    const int row = blockIdx.x;          // b*K + k
    const int b   = row >> 7;
    const int t   = threadIdx.x;
    const int lane = t & 31, w = t >> 5;
    const unsigned lmask_lt = (1u << lane) - 1u;
    const float* gp = points + (size_t)b * N * 3;

    const float cx = g_centers[row * 3 + 0];
    const float cy = g_centers[row * 3 + 1];
    const float cz = g_centers[row * 3 + 2];
    const float cc = __fmaf_rn(cz, cz, __fmaf_rn(cy, cy, __fmul_rn(cx, cx)));

    // Pass 1: keys -> smem; per-thread min for the initial probe estimate
    unsigned tmin = 0xffffffffu;
#pragma unroll 4
    for (int j = 0; j < N / 256; j++) {
        int n = t + j * 256;
        float px = gp[3 * n + 0], py = gp[3 * n + 1], pz = gp[3 * n + 2];
        unsigned key = d2key(px, py, pz, cx, cy, cz, cc);
        s_key[n] = key;
        tmin = min(tmin, key);
    }
    tmin = __reduce_min_sync(0xffffffffu, tmin);
    if (lane == 0) s_wmin[w] = tmin;
    __syncthreads();

    // Initial probe: max of the 8 warp-min keys (~population rank 250-800)
    unsigned probe = 0u;
#pragma unroll
    for (int i = 0; i < 8; i++) probe = max(probe, s_wmin[i]);

    // Exact bisection on key value. Invariants: cnt(lo) < PS, cnt(hiB) >= PS.
    unsigned lo = 0u, hiB = 0xffffffffu, hi = 0u;
    int cnt = 0;
    bool have = false;
    for (int iter = 0; iter < 40; iter++) {
        if (t == 0) s_cnt = 0;
        __syncthreads();
        int c = 0;
#pragma unroll 8
        for (int j = 0; j < N / 256; j++)
            c += (s_key[t + j * 256] <= probe);
        c = __reduce_add_sync(0xffffffffu, c);
        if (lane == 0) atomicAdd(&s_cnt, c);
        __syncthreads();
        cnt = s_cnt;
        __syncthreads();                       // protect next reset (race fix)
        if (cnt >= PS && cnt <= CAPK) { hi = probe; have = true; break; }
        if (cnt < PS) lo = probe; else hiB = probe;
        if (hiB - lo <= 1u) break;             // can't split further
        probe = lo + ((hiB - lo) >> 1);
    }
    if (!have) hi = hiB;                       // cnt(hiB) >= PS guaranteed

    int* out = &g_knn[row * PS];

    if (have) {
        // --- collect survivors from smem keys (warp-aggregated) ---
        if (t == 0) s_cnt = 0;
        __syncthreads();
#pragma unroll 8
        for (int j = 0; j < N / 256; j++) {
            int n = t + j * 256;
            unsigned key = s_key[n];
            bool p = (key <= hi);
            unsigned m = __ballot_sync(0xffffffffu, p);
            if (m) {
                int leader = __ffs(m) - 1;
                int base = 0;
                if (lane == leader) base = atomicAdd(&s_cnt, __popc(m));
                base = __shfl_sync(0xffffffffu, base, leader);
                if (p) {
                    int pos = base + __popc(m & lmask_lt);
                    s_cidx[pos] = n;
                    s_ckey[pos] = key;
                }
            }
        }
        __syncthreads();
        const int C = s_cnt;                   // == verified cnt <= CAPK
        // --- exact stable rank sort ---
        for (int jj = t; jj < C; jj += 256) {
            unsigned kj = s_ckey[jj];
            int      nj = s_cidx[jj];
            int rk = 0;
            for (int m = 0; m < C; m++) {
                unsigned km = s_ckey[m];
                rk += (km < kj) || (km == kj && s_cidx[m] < nj);
            }
            if (rk < PS) out[rk] = nj;
        }
    } else {
        // --- tie-overflow fallback (measure zero): 32 sequential mins over SMEM ---
        if (t == 0) s_last = 0ull;
        __syncthreads();
        for (int sel = 0; sel < PS; sel++) {
            u64 last = s_last;
            u64 best = 0xffffffffffffffffull;
#pragma unroll 8
            for (int j = 0; j < N / 256; j++) {
                int n = t + j * 256;
                u64 v = ((u64)s_key[n] << 32) | (unsigned)n;
                if (v > last && v < best) best = v;
            }
#pragma unroll
            for (int off = 16; off; off >>= 1) {
                u64 o = __shfl_down_sync(0xffffffffu, best, off);
                best = o < best ? o : best;
            }
            if (lane == 0) s_min8[w] = best;
            __syncthreads();
            if (t == 0) {
                u64 m = s_min8[0];
                for (int i = 1; i < 8; i++) m = s_min8[i] < m ? s_min8[i] : m;
                out[sel] = (int)(unsigned)(m & 0xffffffffu);
                s_last = m;
            }
            __syncthreads();
        }
    }
}

// ---------------------------------------------------------------------------
// Epilogues
// ---------------------------------------------------------------------------
extern "C" __global__ void epilogue_i32(int* __restrict__ out, int out_size) {
    int i = blockIdx.x * 256 + threadIdx.x;
    if (i < out_size && i < B * K * PS) out[i] = g_knn[i];
}

extern "C" __global__ void epilogue_f32(float* __restrict__ out, int out_size) {
    int i = blockIdx.x * 256 + threadIdx.x;
    if (i >= out_size) return;
    if (i < B * K * PS) {
        out[i] = (float)g_knn[i];
    } else if (i < B * K * PS + B * K * 3) {
        out[i] = g_centers[i - B * K * PS];
    }
}

// ---------------------------------------------------------------------------
extern "C" void kernel_launch(void* const* d_in, const int* in_sizes, int n_in,
                              void* d_out, int out_size) {
    (void)in_sizes; (void)n_in;
    const float* points = (const float*)d_in[0];

    const int fps_smem = N * 3 * (int)sizeof(float);
    const int knn_smem = N * 4 + CAPK * 4 * 2;

    cudaFuncSetAttribute(fps_kernel,
                         cudaFuncAttributeMaxDynamicSharedMemorySize, fps_smem);
    cudaFuncSetAttribute(knn_kernel,
                         cudaFuncAttributeMaxDynamicSharedMemorySize, knn_smem);

    fps_kernel<<<B, 1024, fps_smem>>>(points);
    knn_kernel<<<B * K, 256, knn_smem>>>(points);

    if (out_size == B * K * PS) {
        int total = B * K * PS;
        epilogue_i32<<<(total + 255) / 256, 256>>>((int*)d_out, out_size);
    } else {
        int total = B * K * PS + B * K * 3;
        int n = total < out_size ? out_size : total;
        epilogue_f32<<<(n + 255) / 256, 256>>>((float*)d_out, out_size);
    }
}

// round 9
// speedup vs baseline: 3.8252x; 3.8252x over previous
#include <cuda_runtime.h>
#include <math_constants.h>
#include <stdint.h>

#define B  32
#define N  8192
#define K  128
#define PS 32

#define CAPC 160        // tight accept window upper bound (rank sort stays cheap)

typedef unsigned long long u64;

// Scratch (allocation-free rule: __device__ globals)
__device__ int   g_fps_idx[B * K];
__device__ float g_centers[B * K * 3];
__device__ int   g_knn[B * K * PS];

// ---------------------------------------------------------------------------
// f32x2 packed helpers (one fma-pipe instr = 2 IEEE .rn ops, bit-identical)
// ---------------------------------------------------------------------------
__device__ __forceinline__ u64 pack2(float lo, float hi) {
    u64 r; asm("mov.b64 %0, {%1, %2};" : "=l"(r) : "f"(lo), "f"(hi)); return r;
}
__device__ __forceinline__ float2 unpack2(u64 v) {
    float2 f; asm("mov.b64 {%0, %1}, %2;" : "=f"(f.x), "=f"(f.y) : "l"(v)); return f;
}
__device__ __forceinline__ u64 add2(u64 a, u64 b) {
    u64 d; asm("add.rn.f32x2 %0, %1, %2;" : "=l"(d) : "l"(a), "l"(b)); return d;
}
__device__ __forceinline__ u64 mul2(u64 a, u64 b) {
    u64 d; asm("mul.rn.f32x2 %0, %1, %2;" : "=l"(d) : "l"(a), "l"(b)); return d;
}
__device__ __forceinline__ u64 fma2(u64 a, u64 b, u64 c) {
    u64 d; asm("fma.rn.f32x2 %0, %1, %2, %3;" : "=l"(d) : "l"(a), "l"(b), "l"(c)); return d;
}

// ---------------------------------------------------------------------------
// FPS: one block/batch, 1024 threads, f32x2 math. NO smem atomics:
// per-warp (REDUX max value, REDUX min index) -> 32 slots -> warp0 reduces.
// Exact jnp.argmax first-occurrence semantics.
// ---------------------------------------------------------------------------
extern "C" __global__ void __launch_bounds__(1024, 1)
fps_kernel(const float* __restrict__ points) {
    extern __shared__ float pts[];      // [N*3] = 96KB
    __shared__ unsigned s_v[32];
    __shared__ int      s_i[32];
    __shared__ int      s_cur;

    const int b = blockIdx.x;
    const int t = threadIdx.x;
    const float* gp = points + (size_t)b * N * 3;

    for (int i = t; i < N * 3; i += 1024) pts[i] = gp[i];
    __syncthreads();

    u64 px2[4], py2[4], pz2[4];
    float md[8];
#pragma unroll
    for (int j = 0; j < 4; j++) {
        int nlo = t + (2 * j) * 1024;
        int nhi = t + (2 * j + 1) * 1024;
        px2[j] = pack2(pts[3 * nlo + 0], pts[3 * nhi + 0]);
        py2[j] = pack2(pts[3 * nlo + 1], pts[3 * nhi + 1]);
        pz2[j] = pack2(pts[3 * nlo + 2], pts[3 * nhi + 2]);
        md[2 * j] = CUDART_INF_F; md[2 * j + 1] = CUDART_INF_F;
    }

    int cur = 0;
    const int lane = t & 31, w = t >> 5;
    for (int k = 0; k < K; k++) {
        float cx = pts[3 * cur + 0];
        float cy = pts[3 * cur + 1];
        float cz = pts[3 * cur + 2];
        if (t == 0) {
            g_fps_idx[b * K + k] = cur;
            g_centers[(b * K + k) * 3 + 0] = cx;
            g_centers[(b * K + k) * 3 + 1] = cy;
            g_centers[(b * K + k) * 3 + 2] = cz;
        }
        u64 nc2x = pack2(-cx, -cx);
        u64 nc2y = pack2(-cy, -cy);
        u64 nc2z = pack2(-cz, -cz);
#pragma unroll
        for (int j = 0; j < 4; j++) {
            u64 dx = add2(px2[j], nc2x);
            u64 dy = add2(py2[j], nc2y);
            u64 dz = add2(pz2[j], nc2z);
            u64 d  = mul2(dx, dx);
            d = fma2(dy, dy, d);
            d = fma2(dz, dz, d);
            float2 f = unpack2(d);
            md[2 * j]     = fminf(md[2 * j],     f.x);
            md[2 * j + 1] = fminf(md[2 * j + 1], f.y);
        }
        float tv = fmaxf(fmaxf(fmaxf(md[0], md[1]), fmaxf(md[2], md[3])),
                         fmaxf(fmaxf(md[4], md[5]), fmaxf(md[6], md[7])));
        // nonneg float bits are order-preserving as uint
        unsigned tb = __float_as_uint(tv);
        unsigned wv = __reduce_max_sync(0xffffffffu, tb);
        unsigned li = 0xffffffffu;
        if (tb == wv) {
#pragma unroll
            for (int s = 0; s < 8; s++)
                if (__float_as_uint(md[s]) == wv) li = min(li, (unsigned)(t + s * 1024));
        }
        li = __reduce_min_sync(0xffffffffu, li);
        if (lane == 0) { s_v[w] = wv; s_i[w] = (int)li; }
        __syncthreads();
        if (w == 0) {
            unsigned v = s_v[lane];
            int     ix = s_i[lane];
            unsigned m = __reduce_max_sync(0xffffffffu, v);
            unsigned cand = (v == m) ? (unsigned)ix : 0xffffffffu;
            unsigned mi = __reduce_min_sync(0xffffffffu, cand);
            if (lane == 0) s_cur = (int)mi;
        }
        __syncthreads();
        cur = s_cur;
    }
}

// ---------------------------------------------------------------------------
// Exact key (explicit intrinsics, bit-identical everywhere it is called)
// ---------------------------------------------------------------------------
__device__ __forceinline__ unsigned f2key(float f) {
    unsigned bits = __float_as_uint(f);
    return (bits & 0x80000000u) ? ~bits : (bits | 0x80000000u);
}
__device__ __forceinline__ unsigned d2key(float px, float py, float pz,
                                          float cx, float cy, float cz, float cc) {
    float pp  = __fmaf_rn(pz, pz, __fmaf_rn(py, py, __fmul_rn(px, px)));
    float dot = __fmaf_rn(cz, pz, __fmaf_rn(cy, py, __fmul_rn(cx, px)));
    float d2  = __fmaf_rn(-2.0f, dot, __fadd_rn(cc, pp));
    return f2key(d2);
}

// ---------------------------------------------------------------------------
// KNN: 1 row/CTA, 256 threads. Full u32 keys in SMEM. Threshold found by
// INTERPOLATED search in d2 domain (cnt ~ d2^1.5), bisection every 3rd iter
// for guaranteed progress; tight accept window [PS, CAPC] keeps the exact
// stable rank sort cheap. Tie-overflow fallback over SMEM keys.
// ---------------------------------------------------------------------------
extern "C" __global__ void __launch_bounds__(256)
knn_kernel(const float* __restrict__ points) {
    extern __shared__ char sm[];
    unsigned* s_key  = (unsigned*)sm;                       // N*4   = 32KB
    int*      s_cidx = (int*)(sm + N * 4);                  // CAPC
    unsigned* s_ckey = (unsigned*)(sm + N * 4 + CAPC * 4);  // CAPC

    __shared__ unsigned s_wmin[8];
    __shared__ int      s_cnt;
    __shared__ u64      s_min8[8];
    __shared__ u64      s_last;

    const int row = blockIdx.x;          // b*K + k
    const int b   = row >> 7;
    const int t   = threadIdx.x;
    const int lane = t & 31, w = t >> 5;
    const unsigned lmask_lt = (1u << lane) - 1u;
    const float* gp = points + (size_t)b * N * 3;

    const float cx = g_centers[row * 3 + 0];
    const float cy = g_centers[row * 3 + 1];
    const float cz = g_centers[row * 3 + 2];
    const float cc = __fmaf_rn(cz, cz, __fmaf_rn(cy, cy, __fmul_rn(cx, cx)));

    // Pass 1: keys -> smem; per-thread min for initial probe
    unsigned tmin = 0xffffffffu;
#pragma unroll 4
    for (int j = 0; j < N / 256; j++) {
        int n = t + j * 256;
        float px = gp[3 * n + 0], py = gp[3 * n + 1], pz = gp[3 * n + 2];
        unsigned key = d2key(px, py, pz, cx, cy, cz, cc);
        s_key[n] = key;
        tmin = min(tmin, key);
    }
    tmin = __reduce_min_sync(0xffffffffu, tmin);
    if (lane == 0) s_wmin[w] = tmin;
    __syncthreads();

    // Initial probe: max of 8 warp-min keys (cnt >= 8 guaranteed at probe)
    unsigned probe = 0u;
#pragma unroll
    for (int i = 0; i < 8; i++) probe = max(probe, s_wmin[i]);

    // Search for hi with cnt(hi) in [PS, CAPC]. Brackets: (klo,clo) cnt<PS,
    // (khi,chi) cnt>CAPC. Interpolation in d2: d_t = d * (64/cnt)^(2/3).
    unsigned klo = 0u, khi = 0xffffffffu;
    int clo = 0, chi = N;
    unsigned hi = 0u;
    bool have = false;
    for (int iter = 0; iter < 24; iter++) {
        if (t == 0) s_cnt = 0;
        __syncthreads();
        int c = 0;
#pragma unroll 8
        for (int j = 0; j < N / 256; j++)
            c += (s_key[t + j * 256] <= probe);
        c = __reduce_add_sync(0xffffffffu, c);
        if (lane == 0) atomicAdd(&s_cnt, c);
        __syncthreads();
        int cnt = s_cnt;
        __syncthreads();                       // protect next reset
        if (cnt >= PS && cnt <= CAPC) { hi = probe; have = true; break; }
        if (cnt < PS) { klo = probe; clo = cnt; }
        else          { khi = probe; chi = cnt; }
        if (khi - klo <= 1u) break;

        unsigned next = klo + ((khi - klo) >> 1);   // default: bisect bits
        if ((iter % 3) != 2) {
            // interpolation in d2 domain (positive-d2 keys only)
            float cand = -1.0f, dlo = 0.0f, dhi = 0.0f;
            bool lo_ok = (klo >= 0x80000000u);
            bool hi_ok = (khi >= 0x80000000u) && (khi != 0xffffffffu);
            if (lo_ok) dlo = __uint_as_float(klo & 0x7fffffffu);
            if (hi_ok) dhi = __uint_as_float(khi & 0x7fffffffu);
            if (hi_ok && chi > 0) {
                cand = dhi * __powf(64.0f / (float)chi, 0.6666667f);
            } else if (lo_ok && clo > 0 && dlo > 0.0f) {
                cand = dlo * __powf(64.0f / (float)clo, 0.6666667f);
            }
            if (cand > 0.0f) {
                unsigned ck = __float_as_uint(cand) | 0x80000000u;
                if (ck > klo && ck < khi) next = ck;
            }
        }
        probe = next;
    }

    int* out = &g_knn[row * PS];

    if (have) {
        // --- collect survivors from smem keys (warp-aggregated) ---
        if (t == 0) s_cnt = 0;
        __syncthreads();
#pragma unroll 8
        for (int j = 0; j < N / 256; j++) {
            int n = t + j * 256;
            unsigned key = s_key[n];
            bool p = (key <= hi);
            unsigned m = __ballot_sync(0xffffffffu, p);
            if (m) {
                int leader = __ffs(m) - 1;
                int base = 0;
                if (lane == leader) base = atomicAdd(&s_cnt, __popc(m));
                base = __shfl_sync(0xffffffffu, base, leader);
                if (p) {
                    int pos = base + __popc(m & lmask_lt);
                    if (pos < CAPC) { s_cidx[pos] = n; s_ckey[pos] = key; }
                }
            }
        }
        __syncthreads();
        const int C = min(s_cnt, CAPC);        // == verified cnt (<= CAPC)
        // --- exact stable rank sort (C <= 160: trivial) ---
        for (int jj = t; jj < C; jj += 256) {
            unsigned kj = s_ckey[jj];
            int      nj = s_cidx[jj];
            int rk = 0;
            for (int m = 0; m < C; m++) {
                unsigned km = s_ckey[m];
                rk += (km < kj) || (km == kj && s_cidx[m] < nj);
            }
            if (rk < PS) out[rk] = nj;
        }
    } else {
        // --- fallback (rare): 32 sequential lexicographic mins over SMEM ---
        if (t == 0) s_last = 0ull;
        __syncthreads();
        for (int sel = 0; sel < PS; sel++) {
            u64 last = s_last;
            u64 best = 0xffffffffffffffffull;
#pragma unroll 8
            for (int j = 0; j < N / 256; j++) {
                int n = t + j * 256;
                u64 v = ((u64)s_key[n] << 32) | (unsigned)n;
                if (v > last && v < best) best = v;
            }
#pragma unroll
            for (int off = 16; off; off >>= 1) {
                u64 o = __shfl_down_sync(0xffffffffu, best, off);
                best = o < best ? o : best;
            }
            if (lane == 0) s_min8[w] = best;
            __syncthreads();
            if (t == 0) {
                u64 m = s_min8[0];
                for (int i = 1; i < 8; i++) m = s_min8[i] < m ? s_min8[i] : m;
                out[sel] = (int)(unsigned)(m & 0xffffffffu);
                s_last = m;
            }
            __syncthreads();
        }
    }
}

// ---------------------------------------------------------------------------
// Epilogues
// ---------------------------------------------------------------------------
extern "C" __global__ void epilogue_i32(int* __restrict__ out, int out_size) {
    int i = blockIdx.x * 256 + threadIdx.x;
    if (i < out_size && i < B * K * PS) out[i] = g_knn[i];
}

extern "C" __global__ void epilogue_f32(float* __restrict__ out, int out_size) {
    int i = blockIdx.x * 256 + threadIdx.x;
    if (i >= out_size) return;
    if (i < B * K * PS) {
        out[i] = (float)g_knn[i];
    } else if (i < B * K * PS + B * K * 3) {
        out[i] = g_centers[i - B * K * PS];
    }
}

// ---------------------------------------------------------------------------
extern "C" void kernel_launch(void* const* d_in, const int* in_sizes, int n_in,
                              void* d_out, int out_size) {
    (void)in_sizes; (void)n_in;
    const float* points = (const float*)d_in[0];

    const int fps_smem = N * 3 * (int)sizeof(float);
    const int knn_smem = N * 4 + CAPC * 4 * 2;

    cudaFuncSetAttribute(fps_kernel,
                         cudaFuncAttributeMaxDynamicSharedMemorySize, fps_smem);
    cudaFuncSetAttribute(knn_kernel,
                         cudaFuncAttributeMaxDynamicSharedMemorySize, knn_smem);

    fps_kernel<<<B, 1024, fps_smem>>>(points);
    knn_kernel<<<B * K, 256, knn_smem>>>(points);

    if (out_size == B * K * PS) {
        int total = B * K * PS;
        epilogue_i32<<<(total + 255) / 256, 256>>>((int*)d_out, out_size);
    } else {
        int total = B * K * PS + B * K * 3;
        int n = total < out_size ? out_size : total;
        epilogue_f32<<<(n + 255) / 256, 256>>>((float*)d_out, out_size);
    }
}